// round 1
// baseline (speedup 1.0000x reference)
#include <cuda_runtime.h>
#include <math.h>

#define DIMS 1024
#define HEAD 16
#define HD   64
#define CTX  2048
#define BATCH 2
#define MROWS (BATCH*CTX)          // 4096
#define OUT_ELEMS (MROWS*DIMS)     // 4,194,304
#define QK_ELEMS  ((size_t)BATCH*HEAD*CTX*CTX)  // 134,217,728

// ---- scratch (alloc-free: device globals) ----
__device__ float g_q [MROWS*DIMS];
__device__ float g_k [MROWS*DIMS];
__device__ float g_v [MROWS*DIMS];
__device__ float g_wv[MROWS*DIMS];
__device__ float g_o1[MROWS*DIMS];
__device__ float g_qk_fallback[QK_ELEMS];  // used only if harness checks just `out`

// ============================================================
// Generic C[M,N] = A[M,K] @ B[N,K]^T + bias   (row-major, NT)
// 64x64 block tile, BK=16, 256 threads, 4x4 microtile
// ============================================================
__global__ void __launch_bounds__(256) gemm_nt(
    const float* __restrict__ A, const float* __restrict__ B,
    const float* __restrict__ bias, float* __restrict__ C,
    int M, int N, int K)
{
    __shared__ float As[16][64];
    __shared__ float Bs[16][64];
    int t = threadIdx.x;
    int row0 = blockIdx.y * 64, col0 = blockIdx.x * 64;
    int lr = t >> 2;          // 0..63  load row
    int lc = (t & 3) * 4;     // 0,4,8,12 load col (k)
    int tx = t & 15, ty = t >> 4;
    float acc[4][4] = {};

    for (int k0 = 0; k0 < K; k0 += 16) {
        float4 a = *(const float4*)(A + (size_t)(row0 + lr) * K + k0 + lc);
        float4 b = *(const float4*)(B + (size_t)(col0 + lr) * K + k0 + lc);
        As[lc+0][lr]=a.x; As[lc+1][lr]=a.y; As[lc+2][lr]=a.z; As[lc+3][lr]=a.w;
        Bs[lc+0][lr]=b.x; Bs[lc+1][lr]=b.y; Bs[lc+2][lr]=b.z; Bs[lc+3][lr]=b.w;
        __syncthreads();
        #pragma unroll
        for (int kk = 0; kk < 16; kk++) {
            float4 av = *(const float4*)&As[kk][ty*4];
            float4 bv = *(const float4*)&Bs[kk][tx*4];
            float pa[4] = {av.x, av.y, av.z, av.w};
            float pb[4] = {bv.x, bv.y, bv.z, bv.w};
            #pragma unroll
            for (int i = 0; i < 4; i++)
                #pragma unroll
                for (int j = 0; j < 4; j++)
                    acc[i][j] += pa[i] * pb[j];
        }
        __syncthreads();
    }
    float4 bb = make_float4(0.f,0.f,0.f,0.f);
    if (bias) bb = *(const float4*)(bias + col0 + tx*4);
    #pragma unroll
    for (int i = 0; i < 4; i++) {
        int r = row0 + ty*4 + i;
        float4 o = make_float4(acc[i][0]+bb.x, acc[i][1]+bb.y,
                               acc[i][2]+bb.z, acc[i][3]+bb.w);
        *(float4*)(C + (size_t)r * N + col0 + tx*4) = o;
    }
}

// ============================================================
// Logits: qk[bh,i,j] = s^2 * (q_i . k_j) * zero_gate(j)
// Per (b,h): M=N=2048, K=64 (one full-K smem tile)
// ============================================================
__global__ void __launch_bounds__(256) logits_kernel(
    const float* __restrict__ q, const float* __restrict__ k,
    const float* __restrict__ factor, float* __restrict__ qk)
{
    int bh = blockIdx.z, b = bh >> 4, h = bh & 15;
    int row0 = blockIdx.y * 64, col0 = blockIdx.x * 64;
    const float* A = q + (size_t)b * CTX * DIMS + h * HD;
    const float* B = k + (size_t)b * CTX * DIMS + h * HD;

    __shared__ float As[64][64];  // [kdim][row]
    __shared__ float Bs[64][64];  // [kdim][col]
    __shared__ float zf[64];

    int t = threadIdx.x;
    int lr = t >> 2, lc = (t & 3) * 4;
    #pragma unroll
    for (int kc = 0; kc < 64; kc += 16) {
        float4 a = *(const float4*)(A + (size_t)(row0 + lr) * DIMS + kc + lc);
        float4 bv = *(const float4*)(B + (size_t)(col0 + lr) * DIMS + kc + lc);
        As[kc+lc+0][lr]=a.x; As[kc+lc+1][lr]=a.y; As[kc+lc+2][lr]=a.z; As[kc+lc+3][lr]=a.w;
        Bs[kc+lc+0][lr]=bv.x; Bs[kc+lc+1][lr]=bv.y; Bs[kc+lc+2][lr]=bv.z; Bs[kc+lc+3][lr]=bv.w;
    }
    if (t < 64) {
        float kf = k[(size_t)(b * CTX + col0 + t) * DIMS + h * HD];
        float f = *factor;
        float zfac = fminf(fmaxf(log1pf(expf(f)), 0.f), 0.001f);
        zf[t] = (kf == 0.f) ? zfac : 1.f;
    }
    __syncthreads();

    int tx = t & 15, ty = t >> 4;
    float acc[4][4] = {};
    #pragma unroll
    for (int kk = 0; kk < 64; kk++) {
        float4 av = *(const float4*)&As[kk][ty*4];
        float4 bv = *(const float4*)&Bs[kk][tx*4];
        float pa[4] = {av.x, av.y, av.z, av.w};
        float pb[4] = {bv.x, bv.y, bv.z, bv.w};
        #pragma unroll
        for (int i = 0; i < 4; i++)
            #pragma unroll
            for (int j = 0; j < 4; j++)
                acc[i][j] += pa[i] * pb[j];
    }
    const float S  = 0.35355339059327373f;   // 64^-0.25
    const float S2 = S * S;
    float* Cb = qk + (size_t)bh * CTX * CTX;
    float z0 = zf[tx*4+0], z1 = zf[tx*4+1], z2 = zf[tx*4+2], z3 = zf[tx*4+3];
    #pragma unroll
    for (int i = 0; i < 4; i++) {
        int r = row0 + ty*4 + i;
        float4 o = make_float4(acc[i][0]*S2*z0, acc[i][1]*S2*z1,
                               acc[i][2]*S2*z2, acc[i][3]*S2*z3);
        *(float4*)(Cb + (size_t)r * CTX + col0 + tx*4) = o;
    }
}

// ============================================================
// Fused softmax + AV: wv[b,q, h*64+d] = softmax(qk[bh,q,:]) @ v[b,:,h*64+d]
// Block: 64 query rows x full hd=64 output cols; pass1 = rowmax,
// pass2 = streaming exp + rowsum accumulated during the k-loop.
// ============================================================
__global__ void __launch_bounds__(256) av_kernel(
    const float* __restrict__ qkbuf, const float* __restrict__ v,
    float* __restrict__ wv)
{
    int bh = blockIdx.y, b = bh >> 4, h = bh & 15;
    int row0 = blockIdx.x * 64;
    const float* L = qkbuf + (size_t)bh * CTX * CTX;

    __shared__ float Ps[16][64];
    __shared__ float Vs[16][64];
    __shared__ float red[64][4];
    __shared__ float rowm[64];
    __shared__ float rowinv[64];

    int t = threadIdx.x;
    int lr = t >> 2, l4 = t & 3;

    // ---- pass 1: row max ----
    const float4* Lr4 = (const float4*)(L + (size_t)(row0 + lr) * CTX);
    float m = -3.4e38f;
    for (int jj = l4; jj < CTX/4; jj += 4) {
        float4 x = Lr4[jj];
        m = fmaxf(m, fmaxf(fmaxf(x.x, x.y), fmaxf(x.z, x.w)));
    }
    red[lr][l4] = m;
    __syncthreads();
    if (t < 64)
        rowm[t] = fmaxf(fmaxf(red[t][0], red[t][1]), fmaxf(red[t][2], red[t][3]));
    __syncthreads();

    // ---- pass 2: streaming exp + AV gemm + rowsum ----
    float mrow = rowm[lr];
    float psum = 0.f;
    int tx = t & 15, ty = t >> 4;
    int vr = t >> 4, vc = (t & 15) * 4;   // V-tile loader: 16 rows x 64 cols
    float acc[4][4] = {};

    for (int k0 = 0; k0 < CTX; k0 += 16) {
        float4 x = *(const float4*)(L + (size_t)(row0 + lr) * CTX + k0 + l4*4);
        float e0 = __expf(x.x - mrow), e1 = __expf(x.y - mrow);
        float e2 = __expf(x.z - mrow), e3 = __expf(x.w - mrow);
        psum += (e0 + e1) + (e2 + e3);
        Ps[l4*4+0][lr] = e0; Ps[l4*4+1][lr] = e1;
        Ps[l4*4+2][lr] = e2; Ps[l4*4+3][lr] = e3;
        float4 vv = *(const float4*)(v + (size_t)(b * CTX + k0 + vr) * DIMS + h * HD + vc);
        *(float4*)&Vs[vr][vc] = vv;
        __syncthreads();
        #pragma unroll
        for (int kk = 0; kk < 16; kk++) {
            float4 p  = *(const float4*)&Ps[kk][ty*4];
            float4 vb = *(const float4*)&Vs[kk][tx*4];
            float pa[4] = {p.x, p.y, p.z, p.w};
            float pb[4] = {vb.x, vb.y, vb.z, vb.w};
            #pragma unroll
            for (int i = 0; i < 4; i++)
                #pragma unroll
                for (int j = 0; j < 4; j++)
                    acc[i][j] += pa[i] * pb[j];
        }
        __syncthreads();
    }
    red[lr][l4] = psum;
    __syncthreads();
    if (t < 64)
        rowinv[t] = 1.f / ((red[t][0] + red[t][1]) + (red[t][2] + red[t][3]));
    __syncthreads();
    #pragma unroll
    for (int i = 0; i < 4; i++) {
        int r = row0 + ty*4 + i;
        float sc = rowinv[ty*4 + i];
        float4 o = make_float4(acc[i][0]*sc, acc[i][1]*sc, acc[i][2]*sc, acc[i][3]*sc);
        *(float4*)(wv + (size_t)(b * CTX + r) * DIMS + h * HD + tx*4) = o;
    }
}

// ============================================================
extern "C" void kernel_launch(void* const* d_in, const int* in_sizes, int n_in,
                              void* d_out, int out_size)
{
    const float* x    = (const float*)d_in[0];
    const float* Wq   = (const float*)d_in[1];
    const float* bq   = (const float*)d_in[2];
    const float* Wk   = (const float*)d_in[3];
    const float* Wv   = (const float*)d_in[4];
    const float* bv   = (const float*)d_in[5];
    const float* Wout = (const float*)d_in[6];
    const float* bout = (const float*)d_in[7];
    const float* factor = (const float*)d_in[8];

    float *qp, *kp, *vp, *wvp, *o1p, *qkfb;
    cudaGetSymbolAddress((void**)&qp,  g_q);
    cudaGetSymbolAddress((void**)&kp,  g_k);
    cudaGetSymbolAddress((void**)&vp,  g_v);
    cudaGetSymbolAddress((void**)&wvp, g_wv);
    cudaGetSymbolAddress((void**)&o1p, g_o1);
    cudaGetSymbolAddress((void**)&qkfb, g_qk_fallback);

    float* out = (float*)d_out;
    float* qkdst = ((size_t)out_size >= (size_t)OUT_ELEMS + QK_ELEMS)
                 ? (out + OUT_ELEMS) : qkfb;

    dim3 gp(DIMS/64, MROWS/64);   // (16, 64)
    gemm_nt<<<gp, 256>>>(x, Wq, bq,      qp, MROWS, DIMS, DIMS);
    gemm_nt<<<gp, 256>>>(x, Wk, nullptr, kp, MROWS, DIMS, DIMS);
    gemm_nt<<<gp, 256>>>(x, Wv, bv,      vp, MROWS, DIMS, DIMS);

    dim3 gl(CTX/64, CTX/64, BATCH*HEAD); // (32, 32, 32)
    logits_kernel<<<gl, 256>>>(qp, kp, factor, qkdst);

    dim3 ga(CTX/64, BATCH*HEAD);         // (32, 32)
    av_kernel<<<ga, 256>>>(qkdst, vp, wvp);

    gemm_nt<<<gp, 256>>>(wvp, Wout, bout, o1p, MROWS, DIMS, DIMS);
    gemm_nt<<<gp, 256>>>(o1p, Wout, bout, out, MROWS, DIMS, DIMS);
}

// round 2
// speedup vs baseline: 1.1392x; 1.1392x over previous
#include <cuda_runtime.h>
#include <math.h>

#define DIMS 1024
#define HEAD 16
#define HD   64
#define CTX  2048
#define BATCH 2
#define MROWS (BATCH*CTX)          // 4096
#define OUT_ELEMS (MROWS*DIMS)     // 4,194,304
#define QK_ELEMS  ((size_t)BATCH*HEAD*CTX*CTX)  // 134,217,728

// ---- scratch (alloc-free: device globals) ----
__device__ float g_q [MROWS*DIMS];
__device__ float g_k [MROWS*DIMS];
__device__ float g_v [MROWS*DIMS];
__device__ float g_wv[MROWS*DIMS];
__device__ float g_o1[MROWS*DIMS];
__device__ float g_qk_fallback[QK_ELEMS];

// ============================================================
// Projection GEMM: C[M,N] = A[M,K] @ B[N,K]^T + bias
// 128x64 tile, BK=16, 256 threads, 8x4 microtile, reg prefetch
// ============================================================
__global__ void __launch_bounds__(256) gemm_nt(
    const float* __restrict__ A, const float* __restrict__ B,
    const float* __restrict__ bias, float* __restrict__ C,
    int M, int N, int K)
{
    __shared__ float As[16][128];
    __shared__ float Bs[16][64];
    int t = threadIdx.x;
    int row0 = blockIdx.y * 128, col0 = blockIdx.x * 64;
    int lr = t >> 1, lc = (t & 1) * 8;     // A loader: 2 thr/row
    int br = t >> 2, bc = (t & 3) * 4;     // B loader: 4 thr/row
    int tx = t & 15, ty = t >> 4;          // compute: col=tx*4, row=ty*8
    float acc[8][4] = {};

    const float* Ap = A + (size_t)(row0 + lr) * K + lc;
    const float* Bp = B + (size_t)(col0 + br) * K + bc;

    float4 a0 = *(const float4*)(Ap);
    float4 a1 = *(const float4*)(Ap + 4);
    float4 b0 = *(const float4*)(Bp);

    for (int k0 = 0; k0 < K; k0 += 16) {
        As[lc+0][lr]=a0.x; As[lc+1][lr]=a0.y; As[lc+2][lr]=a0.z; As[lc+3][lr]=a0.w;
        As[lc+4][lr]=a1.x; As[lc+5][lr]=a1.y; As[lc+6][lr]=a1.z; As[lc+7][lr]=a1.w;
        Bs[bc+0][br]=b0.x; Bs[bc+1][br]=b0.y; Bs[bc+2][br]=b0.z; Bs[bc+3][br]=b0.w;
        __syncthreads();
        if (k0 + 16 < K) {
            a0 = *(const float4*)(Ap + k0 + 16);
            a1 = *(const float4*)(Ap + k0 + 20);
            b0 = *(const float4*)(Bp + k0 + 16);
        }
        #pragma unroll
        for (int kk = 0; kk < 16; kk++) {
            float4 av0 = *(const float4*)&As[kk][ty*8];
            float4 av1 = *(const float4*)&As[kk][ty*8+4];
            float4 bv  = *(const float4*)&Bs[kk][tx*4];
            float pa[8] = {av0.x,av0.y,av0.z,av0.w, av1.x,av1.y,av1.z,av1.w};
            float pb[4] = {bv.x, bv.y, bv.z, bv.w};
            #pragma unroll
            for (int i = 0; i < 8; i++)
                #pragma unroll
                for (int j = 0; j < 4; j++)
                    acc[i][j] += pa[i] * pb[j];
        }
        __syncthreads();
    }
    float4 bb = make_float4(0.f,0.f,0.f,0.f);
    if (bias) bb = *(const float4*)(bias + col0 + tx*4);
    #pragma unroll
    for (int i = 0; i < 8; i++) {
        int r = row0 + ty*8 + i;
        float4 o = make_float4(acc[i][0]+bb.x, acc[i][1]+bb.y,
                               acc[i][2]+bb.z, acc[i][3]+bb.w);
        *(float4*)(C + (size_t)r * N + col0 + tx*4) = o;
    }
}

// ============================================================
// Logits: qk[bh,i,j] = s^2 * (q_i . k_j) * zero_gate(j)
// 128x128 tile, K=64 as 2x BK=32, 8x8 microtile
// ============================================================
__global__ void __launch_bounds__(256) logits_kernel(
    const float* __restrict__ q, const float* __restrict__ k,
    const float* __restrict__ factor, float* __restrict__ qk)
{
    int bh = blockIdx.z, b = bh >> 4, h = bh & 15;
    int row0 = blockIdx.y * 128, col0 = blockIdx.x * 128;
    const float* A = q + (size_t)b * CTX * DIMS + h * HD;
    const float* B = k + (size_t)b * CTX * DIMS + h * HD;

    __shared__ float As[32][128];
    __shared__ float Bs[32][128];
    __shared__ float zf[128];

    int t = threadIdx.x;
    int lr = t >> 1, lc = (t & 1) * 16;
    int tx = t & 15, ty = t >> 4;
    float acc[8][8] = {};

    if (t < 128) {
        float kf = k[(size_t)(b * CTX + col0 + t) * DIMS + h * HD];
        float f = *factor;
        float zfac = fminf(fmaxf(log1pf(expf(f)), 0.f), 0.001f);
        zf[t] = (kf == 0.f) ? zfac : 1.f;
    }

    #pragma unroll
    for (int it = 0; it < 2; it++) {
        int kb = it * 32;
        #pragma unroll
        for (int c = 0; c < 16; c += 4) {
            float4 a = *(const float4*)(A + (size_t)(row0 + lr) * DIMS + kb + lc + c);
            float4 bv= *(const float4*)(B + (size_t)(col0 + lr) * DIMS + kb + lc + c);
            As[lc+c+0][lr]=a.x;  As[lc+c+1][lr]=a.y;  As[lc+c+2][lr]=a.z;  As[lc+c+3][lr]=a.w;
            Bs[lc+c+0][lr]=bv.x; Bs[lc+c+1][lr]=bv.y; Bs[lc+c+2][lr]=bv.z; Bs[lc+c+3][lr]=bv.w;
        }
        __syncthreads();
        #pragma unroll
        for (int kk = 0; kk < 32; kk++) {
            float4 av0 = *(const float4*)&As[kk][ty*8];
            float4 av1 = *(const float4*)&As[kk][ty*8+4];
            float4 bv0 = *(const float4*)&Bs[kk][tx*8];
            float4 bv1 = *(const float4*)&Bs[kk][tx*8+4];
            float pa[8] = {av0.x,av0.y,av0.z,av0.w, av1.x,av1.y,av1.z,av1.w};
            float pb[8] = {bv0.x,bv0.y,bv0.z,bv0.w, bv1.x,bv1.y,bv1.z,bv1.w};
            #pragma unroll
            for (int i = 0; i < 8; i++)
                #pragma unroll
                for (int j = 0; j < 8; j++)
                    acc[i][j] += pa[i] * pb[j];
        }
        __syncthreads();
    }
    const float S2 = 0.125f;   // (64^-0.25)^2 = 1/8
    float* Cb = qk + (size_t)bh * CTX * CTX;
    float zc[8];
    #pragma unroll
    for (int j = 0; j < 8; j++) zc[j] = zf[tx*8+j] * S2;
    #pragma unroll
    for (int i = 0; i < 8; i++) {
        int r = row0 + ty*8 + i;
        float4 o0 = make_float4(acc[i][0]*zc[0], acc[i][1]*zc[1], acc[i][2]*zc[2], acc[i][3]*zc[3]);
        float4 o1 = make_float4(acc[i][4]*zc[4], acc[i][5]*zc[5], acc[i][6]*zc[6], acc[i][7]*zc[7]);
        *(float4*)(Cb + (size_t)r * CTX + col0 + tx*8)     = o0;
        *(float4*)(Cb + (size_t)r * CTX + col0 + tx*8 + 4) = o1;
    }
}

// ============================================================
// Online-softmax + AV (single pass over logits)
// 128 query rows x hd=64 per block, k-chunks of 16, 8x4 microtile
// ============================================================
__global__ void __launch_bounds__(256) av_kernel(
    const float* __restrict__ qkbuf, const float* __restrict__ v,
    float* __restrict__ wv)
{
    int bh = blockIdx.y, b = bh >> 4, h = bh & 15;
    int row0 = blockIdx.x * 128;
    const float* L = qkbuf + (size_t)bh * CTX * CTX;

    __shared__ float Ps[16][128];
    __shared__ float Vs[16][64];
    __shared__ float red[128][2];
    __shared__ float mrow[128];
    __shared__ float rsum[128];
    __shared__ float rscale[128];

    int t = threadIdx.x;
    int lr = t >> 1, lh = t & 1, lc = lh * 8;
    int tx = t & 15, ty = t >> 4;
    int vr = t >> 4, vc = (t & 15) * 4;
    float acc[8][4] = {};

    if (t < 128) { mrow[t] = -3.0e38f; rsum[t] = 0.f; }
    __syncthreads();

    for (int k0 = 0; k0 < CTX; k0 += 16) {
        const float* Lr = L + (size_t)(row0 + lr) * CTX + k0 + lc;
        float4 x0 = *(const float4*)(Lr);
        float4 x1 = *(const float4*)(Lr + 4);
        float lm = fmaxf(fmaxf(fmaxf(x0.x,x0.y),fmaxf(x0.z,x0.w)),
                         fmaxf(fmaxf(x1.x,x1.y),fmaxf(x1.z,x1.w)));
        red[lr][lh] = lm;
        float4 vl = *(const float4*)(v + (size_t)(b * CTX + k0 + vr) * DIMS + h * HD + vc);
        *(float4*)&Vs[vr][vc] = vl;
        __syncthreads();

        if (t < 128) {
            float cm = fmaxf(red[t][0], red[t][1]);
            float mo = mrow[t];
            float mn = fmaxf(mo, cm);
            float sc = __expf(mo - mn);
            rscale[t] = sc;
            mrow[t] = mn;
            rsum[t] *= sc;
        }
        __syncthreads();

        float mr = mrow[lr];
        float e0 = __expf(x0.x - mr), e1 = __expf(x0.y - mr);
        float e2 = __expf(x0.z - mr), e3 = __expf(x0.w - mr);
        float e4 = __expf(x1.x - mr), e5 = __expf(x1.y - mr);
        float e6 = __expf(x1.z - mr), e7 = __expf(x1.w - mr);
        Ps[lc+0][lr]=e0; Ps[lc+1][lr]=e1; Ps[lc+2][lr]=e2; Ps[lc+3][lr]=e3;
        Ps[lc+4][lr]=e4; Ps[lc+5][lr]=e5; Ps[lc+6][lr]=e6; Ps[lc+7][lr]=e7;
        red[lr][lh] = ((e0+e1)+(e2+e3)) + ((e4+e5)+(e6+e7));
        __syncthreads();

        if (t < 128) rsum[t] += red[t][0] + red[t][1];

        float sA[8];
        #pragma unroll
        for (int i = 0; i < 8; i++) sA[i] = rscale[ty*8 + i];
        #pragma unroll
        for (int i = 0; i < 8; i++)
            #pragma unroll
            for (int j = 0; j < 4; j++)
                acc[i][j] *= sA[i];

        #pragma unroll
        for (int kk = 0; kk < 16; kk++) {
            float4 p0 = *(const float4*)&Ps[kk][ty*8];
            float4 p1 = *(const float4*)&Ps[kk][ty*8+4];
            float4 vb = *(const float4*)&Vs[kk][tx*4];
            float pa[8] = {p0.x,p0.y,p0.z,p0.w, p1.x,p1.y,p1.z,p1.w};
            float pb[4] = {vb.x, vb.y, vb.z, vb.w};
            #pragma unroll
            for (int i = 0; i < 8; i++)
                #pragma unroll
                for (int j = 0; j < 4; j++)
                    acc[i][j] += pa[i] * pb[j];
        }
        __syncthreads();
    }

    #pragma unroll
    for (int i = 0; i < 8; i++) {
        int r = row0 + ty*8 + i;
        float inv = 1.f / rsum[ty*8 + i];
        float4 o = make_float4(acc[i][0]*inv, acc[i][1]*inv, acc[i][2]*inv, acc[i][3]*inv);
        *(float4*)(wv + (size_t)(b * CTX + r) * DIMS + h * HD + tx*4) = o;
    }
}

// ============================================================
extern "C" void kernel_launch(void* const* d_in, const int* in_sizes, int n_in,
                              void* d_out, int out_size)
{
    const float* x    = (const float*)d_in[0];
    const float* Wq   = (const float*)d_in[1];
    const float* bq   = (const float*)d_in[2];
    const float* Wk   = (const float*)d_in[3];
    const float* Wv   = (const float*)d_in[4];
    const float* bv   = (const float*)d_in[5];
    const float* Wout = (const float*)d_in[6];
    const float* bout = (const float*)d_in[7];
    const float* factor = (const float*)d_in[8];

    float *qp, *kp, *vp, *wvp, *o1p, *qkfb;
    cudaGetSymbolAddress((void**)&qp,  g_q);
    cudaGetSymbolAddress((void**)&kp,  g_k);
    cudaGetSymbolAddress((void**)&vp,  g_v);
    cudaGetSymbolAddress((void**)&wvp, g_wv);
    cudaGetSymbolAddress((void**)&o1p, g_o1);
    cudaGetSymbolAddress((void**)&qkfb, g_qk_fallback);

    float* out = (float*)d_out;
    float* qkdst = ((size_t)out_size >= (size_t)OUT_ELEMS + QK_ELEMS)
                 ? (out + OUT_ELEMS) : qkfb;

    dim3 gp(DIMS/64, MROWS/128);   // (16, 32) = 512 blocks
    gemm_nt<<<gp, 256>>>(x, Wq, bq,      qp, MROWS, DIMS, DIMS);
    gemm_nt<<<gp, 256>>>(x, Wk, nullptr, kp, MROWS, DIMS, DIMS);
    gemm_nt<<<gp, 256>>>(x, Wv, bv,      vp, MROWS, DIMS, DIMS);

    dim3 gl(CTX/128, CTX/128, BATCH*HEAD); // (16, 16, 32)
    logits_kernel<<<gl, 256>>>(qp, kp, factor, qkdst);

    dim3 ga(CTX/128, BATCH*HEAD);          // (16, 32) = 512 blocks
    av_kernel<<<ga, 256>>>(qkdst, vp, wvp);

    gemm_nt<<<gp, 256>>>(wvp, Wout, bout, o1p, MROWS, DIMS, DIMS);
    gemm_nt<<<gp, 256>>>(o1p, Wout, bout, out, MROWS, DIMS, DIMS);
}